// round 16
// baseline (speedup 1.0000x reference)
#include <cuda_runtime.h>
#include <cuda_bf16.h>
#include <cuda_fp16.h>
#include <math.h>
#include <stdint.h>

#define B_DIM   4
#define S_DIM   8192
#define H_DIM   4096
#define RATIO   32
#define M_TOT   (B_DIM * S_DIM)      /* 32768 */
#define N_TOT   512

// ---------------- scratch (device globals: no allocs allowed) ----------------
__device__ __align__(16) float  g_mid[(size_t)M_TOT * N_TOT];   // 64 MB
__device__ __align__(16) __half g_Ah [(size_t)M_TOT * H_DIM];   // 256 MB
__device__ __align__(16) __half g_Whi[(size_t)N_TOT * H_DIM];   // 4 MB
__device__ __align__(16) __half g_Wlo[(size_t)N_TOT * H_DIM];   // 4 MB

// ---------------- helpers ----------------
__device__ __forceinline__ uint32_t smem_u32(const void* p) {
    uint32_t a;
    asm("{ .reg .u64 t; cvta.to.shared.u64 t, %1; cvt.u32.u64 %0, t; }" : "=r"(a) : "l"(p));
    return a;
}

#define CP16(dst, src) \
    asm volatile("cp.async.cg.shared.global [%0], [%1], 16;" \
                 :: "r"(dst), "l"(__cvta_generic_to_global((const void*)(src))) : "memory")
#define CP_COMMIT() asm volatile("cp.async.commit_group;" ::: "memory")
#define CP_WAIT(n)  asm volatile("cp.async.wait_group %0;" :: "n"(n) : "memory")

#define LDSM_X4(r, addr)                                                          \
    asm volatile("ldmatrix.sync.aligned.m8n8.x4.shared.b16 {%0,%1,%2,%3}, [%4];"  \
        : "=r"((r)[0]), "=r"((r)[1]), "=r"((r)[2]), "=r"((r)[3]) : "r"(addr))

// m16n8k16 row.col fp16 -> f32 accumulate
#define MMA_F16(c, a, b0, b1)                                                     \
    asm volatile("mma.sync.aligned.m16n8k16.row.col.f32.f16.f16.f32 "             \
        "{%0,%1,%2,%3}, {%4,%5,%6,%7}, {%8,%9}, {%0,%1,%2,%3};"                   \
        : "+f"((c)[0]), "+f"((c)[1]), "+f"((c)[2]), "+f"((c)[3])                  \
        : "r"((a)[0]), "r"((a)[1]), "r"((a)[2]), "r"((a)[3]), "r"(b0), "r"(b1))

// Interleaved BK=32 smem layout: element (r, k16chunk c) of a tile lives at
//   byte_off = (r>>1)*128 + ((( ((r&1)<<2) | c ) ^ ((r>>1)&7)) << 4)
__device__ __forceinline__ uint32_t swz_off(int r, int c) {
    return (uint32_t)(((r >> 1) * 128) +
           (((((r & 1) << 2) | c) ^ ((r >> 1) & 7)) << 4));
}

// ---------------- pre-pass: hidden fp32 -> fp16 ----------------
__global__ __launch_bounds__(256) void convA_kernel(const float* __restrict__ A) {
    size_t base = ((size_t)blockIdx.x * 256 + threadIdx.x) * 8;
    float4 v0 = *(const float4*)(A + base);
    float4 v1 = *(const float4*)(A + base + 4);
    uint4 u;
    __half* hp = (__half*)&u;
    hp[0] = __float2half_rn(v0.x); hp[1] = __float2half_rn(v0.y);
    hp[2] = __float2half_rn(v0.z); hp[3] = __float2half_rn(v0.w);
    hp[4] = __float2half_rn(v1.x); hp[5] = __float2half_rn(v1.y);
    hp[6] = __float2half_rn(v1.z); hp[7] = __float2half_rn(v1.w);
    *(uint4*)(g_Ah + base) = u;
}

// ------ pre-pass: weights fp32 [K, 256]x2 -> fp16 hi/lo, transposed [512, K] --
__global__ __launch_bounds__(256) void convW_kernel(const float* __restrict__ wkv,
                                                    const float* __restrict__ wg) {
    int k = blockIdx.x * 256 + threadIdx.x;   // 0..4095
    int n = blockIdx.y;                       // 0..511
    const float* w = (n < 256) ? wkv : wg;
    float x = w[(size_t)k * 256 + (n & 255)];
    __half h = __float2half_rn(x);
    g_Whi[(size_t)n * H_DIM + k] = h;
    g_Wlo[(size_t)n * H_DIM + k] = __float2half_rn(x - __half2float(h));
}

// ---------------- main GEMM ----------------
// g_mid[M, 512] = hidden @ [w_kv | w_gate]
// BM=128 BN=128 BK=32, 256 threads, 4-stage cp.async ring, one sync/ktile,
// 2 CTAs/SM (co-resident CTA hides barrier bubbles).
// 2-term fp16 split: A * (Bhi + Blo), fp32 accumulate.
#define BK 32
#define NTILES (H_DIM / BK)        /* 128 */
#define OFF_BHI 8192
#define OFF_BLO 16384
#define STAGE_BYTES 24576
#define SMEM_GEMM (4 * STAGE_BYTES)   /* 98304 per CTA */

__global__ __launch_bounds__(256, 2) void gemm_kernel() {
    extern __shared__ __align__(1024) char smem[];
    const uint32_t sb = smem_u32(smem);
    const int tid  = threadIdx.x;
    const int wid  = tid >> 5;
    const int lane = tid & 31;
    const int gID  = lane >> 2;
    const int tig  = lane & 3;
    const int wr   = wid & 3;     // m block: 32 rows
    const int wc   = wid >> 2;    // n block: 64 cols (0..1)
    const int n0 = blockIdx.x * 128;
    const int m0 = blockIdx.y * 128;

    // ---- per-thread cp.async fill addressing ----
    // 512 16B-chunks per 128-row tile; 256 threads handle rows r0 and r0+64.
    const int r0f = tid >> 2, cf = tid & 3;
    const uint32_t dst0 = swz_off(r0f, cf);           // row r0f
    // row r0f+64: (r>>1) increases by 32 -> +4096 bytes, same swizzle key
    const __half* srcA  = g_Ah  + (size_t)(m0 + r0f) * H_DIM + cf * 8;
    const __half* srcBh = g_Whi + (size_t)(n0 + r0f) * H_DIM + cf * 8;
    const __half* srcBl = g_Wlo + (size_t)(n0 + r0f) * H_DIM + cf * 8;
    const size_t row64 = (size_t)64 * H_DIM;

    // ---- per-lane ldmatrix addressing ----
    const int mQ = lane >> 3, l7 = lane & 7;
    const int rA = wr * 32 + (mQ & 1) * 8 + l7;
    const uint32_t aLine = (uint32_t)((rA >> 1) * 128);
    const uint32_t aQ = (uint32_t)((rA & 1) << 2);
    const uint32_t sA = (uint32_t)((rA >> 1) & 7);
    const int cA0 = mQ >> 1;
    const int rB = wc * 64 + (mQ >> 1) * 8 + l7;
    const uint32_t bLine = (uint32_t)((rB >> 1) * 128);
    const uint32_t bQ = (uint32_t)((rB & 1) << 2);
    const uint32_t sB = (uint32_t)((rB >> 1) & 7);
    const int cB0 = mQ & 1;

    float acc[2][8][4];
#pragma unroll
    for (int mt = 0; mt < 2; mt++)
#pragma unroll
        for (int nt = 0; nt < 8; nt++)
#pragma unroll
            for (int j = 0; j < 4; j++) acc[mt][nt][j] = 0.f;

#define FILL_STAGE(stg, kt) do {                                                  \
    const uint32_t st_ = sb + (uint32_t)(stg) * STAGE_BYTES;                      \
    const size_t ko_ = (size_t)(kt) * BK;                                         \
    CP16(st_ + dst0,                  srcA  + ko_);                               \
    CP16(st_ + dst0 + 4096,           srcA  + row64 + ko_);                       \
    CP16(st_ + OFF_BHI + dst0,        srcBh + ko_);                               \
    CP16(st_ + OFF_BHI + dst0 + 4096, srcBh + row64 + ko_);                       \
    CP16(st_ + OFF_BLO + dst0,        srcBl + ko_);                               \
    CP16(st_ + OFF_BLO + dst0 + 4096, srcBl + row64 + ko_);                       \
} while (0)

    FILL_STAGE(0, 0); CP_COMMIT();
    FILL_STAGE(1, 1); CP_COMMIT();
    FILL_STAGE(2, 2); CP_COMMIT();

    for (int kt = 0; kt < NTILES; kt++) {
        const int s = kt & 3;
        if (kt < NTILES - 2)      { CP_WAIT(2); }
        else if (kt == NTILES - 2){ CP_WAIT(1); }
        else                      { CP_WAIT(0); }
        __syncthreads();

        const uint32_t Ahb = sb + (uint32_t)s * STAGE_BYTES;
        const uint32_t Bh  = Ahb + OFF_BHI;
        const uint32_t Bl  = Ahb + OFF_BLO;

#pragma unroll
        for (int kk = 0; kk < 2; kk++) {
            uint32_t ah[2][4];
            const uint32_t aoff =
                aLine + (((aQ | (uint32_t)(2 * kk + cA0)) ^ sA) << 4);
#pragma unroll
            for (int mt = 0; mt < 2; mt++)
                LDSM_X4(ah[mt], Ahb + aoff + mt * 1024);
            const uint32_t boff =
                bLine + (((bQ | (uint32_t)(2 * kk + cB0)) ^ sB) << 4);
#pragma unroll
            for (int p = 0; p < 4; p++) {
                uint32_t bh[4], bl[4];
                LDSM_X4(bh, Bh + boff + p * 1024);
                LDSM_X4(bl, Bl + boff + p * 1024);
#pragma unroll
                for (int mt = 0; mt < 2; mt++) {
                    MMA_F16(acc[mt][2*p],   ah[mt], bh[0], bh[1]);
                    MMA_F16(acc[mt][2*p],   ah[mt], bl[0], bl[1]);
                    MMA_F16(acc[mt][2*p+1], ah[mt], bh[2], bh[3]);
                    MMA_F16(acc[mt][2*p+1], ah[mt], bl[2], bl[3]);
                }
            }
        }

        if (kt + 3 < NTILES) {
            // stage (kt+3)&3 was consumed at iteration kt-1; the barrier at
            // the top of this iteration ordered all its readers before refill.
            FILL_STAGE((kt + 3) & 3, kt + 3);
            CP_COMMIT();
        }
    }

    // ---- epilogue ----
#pragma unroll
    for (int mt = 0; mt < 2; mt++) {
        const int r0 = m0 + wr * 32 + mt * 16 + gID;
#pragma unroll
        for (int nt = 0; nt < 8; nt++) {
            const int c0 = n0 + wc * 64 + nt * 8 + 2 * tig;
            *(float2*)&g_mid[(size_t)r0 * N_TOT + c0] =
                make_float2(acc[mt][nt][0], acc[mt][nt][1]);
            *(float2*)&g_mid[(size_t)(r0 + 8) * N_TOT + c0] =
                make_float2(acc[mt][nt][2], acc[mt][nt][3]);
        }
    }
}

// ---------------- kernel 2: windowed softmax-pool + RoPE ----------------
__global__ void pool_kernel(const float* __restrict__ pbias,
                            float* __restrict__ out)
{
    const int bc = blockIdx.x;       // b * 256 + c
    const int b  = bc >> 8;
    const int c  = bc & 255;
    const int d  = threadIdx.x;      // 0..127

    const float* base = g_mid + (size_t)b * S_DIM * N_TOT;

    float m = -INFINITY, s = 0.f, acc = 0.f;

    if (c > 0) {
        const float* rowp = base + (size_t)(c - 1) * RATIO * N_TOT;
#pragma unroll 4
        for (int j = 0; j < RATIO; j++) {
            float g  = rowp[j * N_TOT + 256 + d] + pbias[j * 128 + d];
            float kv = rowp[j * N_TOT + d];
            float nm = fmaxf(m, g);
            float sc = __expf(m - nm);
            float e  = __expf(g - nm);
            s   = s * sc + e;
            acc = acc * sc + e * kv;
            m = nm;
        }
    }
    {
        const float* rowp = base + (size_t)c * RATIO * N_TOT;
#pragma unroll 4
        for (int j = 0; j < RATIO; j++) {
            float g  = rowp[j * N_TOT + 384 + d] + pbias[(RATIO + j) * 128 + d];
            float kv = rowp[j * N_TOT + 128 + d];
            float nm = fmaxf(m, g);
            float sc = __expf(m - nm);
            float e  = __expf(g - nm);
            s   = s * sc + e;
            acc = acc * sc + e * kv;
            m = nm;
        }
    }

    __shared__ float ps[128];
    ps[d] = acc / s;
    __syncthreads();

    float o;
    if (d < 64) {
        o = ps[d];
    } else {
        const int rd = d - 64;
        const int p  = rd >> 1;
        double inv_freq = exp(-(double)(2 * p) / 64.0 * log(10000.0));
        double ang = (double)(c * RATIO) * inv_freq;
        double sn, cs;
        sincos(ang, &sn, &cs);
        float x  = ps[64 + rd];
        float xp = ps[64 + (rd ^ 1)];
        if ((rd & 1) == 0)
            o = x * (float)cs - xp * (float)sn;
        else
            o = x * (float)cs + xp * (float)sn;
    }
    out[(size_t)bc * 128 + d] = o;
}

// ---------------------------------------------------------------------------
extern "C" void kernel_launch(void* const* d_in, const int* in_sizes, int n_in,
                              void* d_out, int out_size)
{
    const float* hidden = (const float*)d_in[0];   // (4, 8192, 4096)
    const float* w_kv   = (const float*)d_in[1];   // (4096, 256)
    const float* w_gate = (const float*)d_in[2];   // (4096, 256)
    const float* pbias  = (const float*)d_in[3];   // (64, 128)
    float* out = (float*)d_out;                    // (4, 256, 128)

    cudaFuncSetAttribute(gemm_kernel,
                         cudaFuncAttributeMaxDynamicSharedMemorySize, SMEM_GEMM);

    convA_kernel<<<(size_t)M_TOT * H_DIM / (256 * 8), 256>>>(hidden);
    convW_kernel<<<dim3(H_DIM / 256, N_TOT), 256>>>(w_kv, w_gate);

    // grid.x fastest: the 4 column-block CTAs sharing one A row-block are
    // adjacent bids -> concurrent -> A served from L2.
    dim3 ggrid(N_TOT / 128, M_TOT / 128);   // (4, 256)
    gemm_kernel<<<ggrid, 256, SMEM_GEMM>>>();

    pool_kernel<<<B_DIM * (S_DIM / RATIO), 128>>>(pbias, out);
}

// round 17
// speedup vs baseline: 1.0702x; 1.0702x over previous
#include <cuda_runtime.h>
#include <cuda_bf16.h>
#include <cuda_fp16.h>
#include <math.h>
#include <stdint.h>

#define B_DIM   4
#define S_DIM   8192
#define H_DIM   4096
#define RATIO   32
#define M_TOT   (B_DIM * S_DIM)      /* 32768 */
#define N_TOT   512

// ---------------- scratch (device globals: no allocs allowed) ----------------
__device__ __align__(16) float  g_mid[(size_t)M_TOT * N_TOT];   // 64 MB
__device__ __align__(16) __half g_Whi[(size_t)N_TOT * H_DIM];   // 4 MB
__device__ __align__(16) __half g_Wlo[(size_t)N_TOT * H_DIM];   // 4 MB

// ---------------- helpers ----------------
__device__ __forceinline__ uint32_t smem_u32(const void* p) {
    uint32_t a;
    asm("{ .reg .u64 t; cvta.to.shared.u64 t, %1; cvt.u32.u64 %0, t; }" : "=r"(a) : "l"(p));
    return a;
}

#define CP16(dst, src) \
    asm volatile("cp.async.cg.shared.global [%0], [%1], 16;" \
                 :: "r"(dst), "l"(__cvta_generic_to_global((const void*)(src))) : "memory")
#define CP_COMMIT() asm volatile("cp.async.commit_group;" ::: "memory")
#define CP_WAIT(n)  asm volatile("cp.async.wait_group %0;" :: "n"(n) : "memory")

#define LDSM_X4(r, addr)                                                          \
    asm volatile("ldmatrix.sync.aligned.m8n8.x4.shared.b16 {%0,%1,%2,%3}, [%4];"  \
        : "=r"((r)[0]), "=r"((r)[1]), "=r"((r)[2]), "=r"((r)[3]) : "r"(addr))

#define STS128(addr, r0, r1, r2, r3)                                              \
    asm volatile("st.shared.v4.b32 [%0], {%1,%2,%3,%4};"                          \
        :: "r"(addr), "r"(r0), "r"(r1), "r"(r2), "r"(r3) : "memory")

// m16n8k16 row.col fp16 -> f32 accumulate
#define MMA_F16(c, a, b0, b1)                                                     \
    asm volatile("mma.sync.aligned.m16n8k16.row.col.f32.f16.f16.f32 "             \
        "{%0,%1,%2,%3}, {%4,%5,%6,%7}, {%8,%9}, {%0,%1,%2,%3};"                   \
        : "+f"((c)[0]), "+f"((c)[1]), "+f"((c)[2]), "+f"((c)[3])                  \
        : "r"((a)[0]), "r"((a)[1]), "r"((a)[2]), "r"((a)[3]), "r"(b0), "r"(b1))

// Interleaved BK=32 smem layout: element (r, k16chunk c) of a tile lives at
//   byte_off = (r>>1)*128 + ((( ((r&1)<<2) | c ) ^ ((r>>1)&7)) << 4)
__device__ __forceinline__ uint32_t swz_off(int r, int c) {
    return (uint32_t)(((r >> 1) * 128) +
           (((((r & 1) << 2) | c) ^ ((r >> 1) & 7)) << 4));
}

__device__ __forceinline__ uint32_t pack_h2(float x, float y) {
    __half2 h = __float22half2_rn(make_float2(x, y));
    return *(uint32_t*)&h;
}

// ------ pre-pass: weights fp32 [K, 256]x2 -> fp16 hi/lo, transposed [512, K] --
__global__ __launch_bounds__(256) void convW_kernel(const float* __restrict__ wkv,
                                                    const float* __restrict__ wg) {
    int k = blockIdx.x * 256 + threadIdx.x;   // 0..4095
    int n = blockIdx.y;                       // 0..511
    const float* w = (n < 256) ? wkv : wg;
    float x = w[(size_t)k * 256 + (n & 255)];
    __half h = __float2half_rn(x);
    g_Whi[(size_t)n * H_DIM + k] = h;
    g_Wlo[(size_t)n * H_DIM + k] = __float2half_rn(x - __half2float(h));
}

// ---------------- main GEMM (A conversion fused) ----------------
// g_mid[M, 512] = hidden @ [w_kv | w_gate]
// BM=128 BN=128 BK=32, 256 threads, 4-stage ring, one sync/ktile, 2 CTAs/SM.
// A: fp32 LDG 3 ktiles ahead -> regs -> fp16 cvt -> swizzled smem (STS).
// B: cp.async fp16 hi/lo. 2-term fp16 split, fp32 accumulate.
#define BK 32
#define NTILES (H_DIM / BK)        /* 128 */
#define OFF_BHI 8192
#define OFF_BLO 16384
#define STAGE_BYTES 24576
#define SMEM_GEMM (4 * STAGE_BYTES)   /* 98304 per CTA */

__global__ __launch_bounds__(256, 2) void gemm_kernel(const float* __restrict__ A) {
    extern __shared__ __align__(1024) char smem[];
    const uint32_t sb = smem_u32(smem);
    const int tid  = threadIdx.x;
    const int wid  = tid >> 5;
    const int lane = tid & 31;
    const int gID  = lane >> 2;
    const int tig  = lane & 3;
    const int wr   = wid & 3;     // m block: 32 rows
    const int wc   = wid >> 2;    // n block: 64 cols (0..1)
    const int n0 = blockIdx.x * 128;
    const int m0 = blockIdx.y * 128;

    // ---- per-thread fill addressing ----
    // thread (r0f, cf): rows r0f and r0f+64, k-chunk cf (8 elements)
    const int r0f = tid >> 2, cf = tid & 3;
    const uint32_t dst0 = swz_off(r0f, cf);           // +4096 bytes for row+64
    const float* srcA  = A + (size_t)(m0 + r0f) * H_DIM + cf * 8;
    const __half* srcBh = g_Whi + (size_t)(n0 + r0f) * H_DIM + cf * 8;
    const __half* srcBl = g_Wlo + (size_t)(n0 + r0f) * H_DIM + cf * 8;
    const size_t row64h = (size_t)64 * H_DIM;

    // ---- per-lane ldmatrix addressing ----
    const int mQ = lane >> 3, l7 = lane & 7;
    const int rA = wr * 32 + (mQ & 1) * 8 + l7;
    const uint32_t aLine = (uint32_t)((rA >> 1) * 128);
    const uint32_t aQ = (uint32_t)((rA & 1) << 2);
    const uint32_t sA = (uint32_t)((rA >> 1) & 7);
    const int cA0 = mQ >> 1;
    const int rB = wc * 64 + (mQ >> 1) * 8 + l7;
    const uint32_t bLine = (uint32_t)((rB >> 1) * 128);
    const uint32_t bQ = (uint32_t)((rB & 1) << 2);
    const uint32_t sB = (uint32_t)((rB >> 1) & 7);
    const int cB0 = mQ & 1;

    float acc[2][8][4];
#pragma unroll
    for (int mt = 0; mt < 2; mt++)
#pragma unroll
        for (int nt = 0; nt < 8; nt++)
#pragma unroll
            for (int j = 0; j < 4; j++) acc[mt][nt][j] = 0.f;

    float4 R[4];   // A fp32 prefetch: rows r0f (R0,R1) and r0f+64 (R2,R3)

#define LDG_A(kt) do {                                                            \
    const float* p_ = srcA + (size_t)(kt) * BK;                                   \
    R[0] = *(const float4*)(p_);                                                  \
    R[1] = *(const float4*)(p_ + 4);                                              \
    R[2] = *(const float4*)(p_ + row64h);                                         \
    R[3] = *(const float4*)(p_ + row64h + 4);                                     \
} while (0)

#define CVT_STS_A(stg) do {                                                       \
    const uint32_t st_ = sb + (uint32_t)(stg) * STAGE_BYTES;                      \
    uint32_t h0 = pack_h2(R[0].x, R[0].y), h1 = pack_h2(R[0].z, R[0].w);          \
    uint32_t h2 = pack_h2(R[1].x, R[1].y), h3 = pack_h2(R[1].z, R[1].w);          \
    STS128(st_ + dst0, h0, h1, h2, h3);                                           \
    h0 = pack_h2(R[2].x, R[2].y); h1 = pack_h2(R[2].z, R[2].w);                   \
    h2 = pack_h2(R[3].x, R[3].y); h3 = pack_h2(R[3].z, R[3].w);                   \
    STS128(st_ + dst0 + 4096, h0, h1, h2, h3);                                    \
} while (0)

#define FILL_B(stg, kt) do {                                                      \
    const uint32_t st_ = sb + (uint32_t)(stg) * STAGE_BYTES;                      \
    const size_t ko_ = (size_t)(kt) * BK;                                         \
    CP16(st_ + OFF_BHI + dst0,        srcBh + ko_);                               \
    CP16(st_ + OFF_BHI + dst0 + 4096, srcBh + row64h + ko_);                      \
    CP16(st_ + OFF_BLO + dst0,        srcBl + ko_);                               \
    CP16(st_ + OFF_BLO + dst0 + 4096, srcBl + row64h + ko_);                      \
} while (0)

    // ---- prologue: stages 0..2 ----
#pragma unroll
    for (int p = 0; p < 3; p++) {
        LDG_A(p);
        CVT_STS_A(p);
        FILL_B(p, p);
        CP_COMMIT();
    }
    LDG_A(3);   // prefetch for stage 3 (stored at end of iter 0)

    for (int kt = 0; kt < NTILES; kt++) {
        const int s = kt & 3;
        if (kt < NTILES - 2)      { CP_WAIT(2); }
        else if (kt == NTILES - 2){ CP_WAIT(1); }
        else                      { CP_WAIT(0); }
        __syncthreads();

        const uint32_t Ahb = sb + (uint32_t)s * STAGE_BYTES;
        const uint32_t Bh  = Ahb + OFF_BHI;
        const uint32_t Bl  = Ahb + OFF_BLO;

#pragma unroll
        for (int kk = 0; kk < 2; kk++) {
            uint32_t ah[2][4];
            const uint32_t aoff =
                aLine + (((aQ | (uint32_t)(2 * kk + cA0)) ^ sA) << 4);
#pragma unroll
            for (int mt = 0; mt < 2; mt++)
                LDSM_X4(ah[mt], Ahb + aoff + mt * 1024);
            const uint32_t boff =
                bLine + (((bQ | (uint32_t)(2 * kk + cB0)) ^ sB) << 4);
#pragma unroll
            for (int p = 0; p < 4; p++) {
                uint32_t bh[4], bl[4];
                LDSM_X4(bh, Bh + boff + p * 1024);
                LDSM_X4(bl, Bl + boff + p * 1024);
#pragma unroll
                for (int mt = 0; mt < 2; mt++) {
                    MMA_F16(acc[mt][2*p],   ah[mt], bh[0], bh[1]);
                    MMA_F16(acc[mt][2*p],   ah[mt], bl[0], bl[1]);
                    MMA_F16(acc[mt][2*p+1], ah[mt], bh[2], bh[3]);
                    MMA_F16(acc[mt][2*p+1], ah[mt], bl[2], bl[3]);
                }
            }
        }

        if (kt + 3 < NTILES) {
            // stage (kt+3)&3 was last read at iter kt-1; the barrier at the
            // top of this iteration ordered all readers before these writes.
            CVT_STS_A((kt + 3) & 3);
            FILL_B((kt + 3) & 3, kt + 3);
            CP_COMMIT();
            if (kt + 4 < NTILES) LDG_A(kt + 4);
        }
    }

    // ---- epilogue ----
#pragma unroll
    for (int mt = 0; mt < 2; mt++) {
        const int r0 = m0 + wr * 32 + mt * 16 + gID;
#pragma unroll
        for (int nt = 0; nt < 8; nt++) {
            const int c0 = n0 + wc * 64 + nt * 8 + 2 * tig;
            *(float2*)&g_mid[(size_t)r0 * N_TOT + c0] =
                make_float2(acc[mt][nt][0], acc[mt][nt][1]);
            *(float2*)&g_mid[(size_t)(r0 + 8) * N_TOT + c0] =
                make_float2(acc[mt][nt][2], acc[mt][nt][3]);
        }
    }
}

// ---------------- kernel 2: windowed softmax-pool + RoPE ----------------
__global__ void pool_kernel(const float* __restrict__ pbias,
                            float* __restrict__ out)
{
    const int bc = blockIdx.x;       // b * 256 + c
    const int b  = bc >> 8;
    const int c  = bc & 255;
    const int d  = threadIdx.x;      // 0..127

    const float* base = g_mid + (size_t)b * S_DIM * N_TOT;

    float m = -INFINITY, s = 0.f, acc = 0.f;

    if (c > 0) {
        const float* rowp = base + (size_t)(c - 1) * RATIO * N_TOT;
#pragma unroll 4
        for (int j = 0; j < RATIO; j++) {
            float g  = rowp[j * N_TOT + 256 + d] + pbias[j * 128 + d];
            float kv = rowp[j * N_TOT + d];
            float nm = fmaxf(m, g);
            float sc = __expf(m - nm);
            float e  = __expf(g - nm);
            s   = s * sc + e;
            acc = acc * sc + e * kv;
            m = nm;
        }
    }
    {
        const float* rowp = base + (size_t)c * RATIO * N_TOT;
#pragma unroll 4
        for (int j = 0; j < RATIO; j++) {
            float g  = rowp[j * N_TOT + 384 + d] + pbias[(RATIO + j) * 128 + d];
            float kv = rowp[j * N_TOT + 128 + d];
            float nm = fmaxf(m, g);
            float sc = __expf(m - nm);
            float e  = __expf(g - nm);
            s   = s * sc + e;
            acc = acc * sc + e * kv;
            m = nm;
        }
    }

    __shared__ float ps[128];
    ps[d] = acc / s;
    __syncthreads();

    float o;
    if (d < 64) {
        o = ps[d];
    } else {
        const int rd = d - 64;
        const int p  = rd >> 1;
        double inv_freq = exp(-(double)(2 * p) / 64.0 * log(10000.0));
        double ang = (double)(c * RATIO) * inv_freq;
        double sn, cs;
        sincos(ang, &sn, &cs);
        float x  = ps[64 + rd];
        float xp = ps[64 + (rd ^ 1)];
        if ((rd & 1) == 0)
            o = x * (float)cs - xp * (float)sn;
        else
            o = x * (float)cs + xp * (float)sn;
    }
    out[(size_t)bc * 128 + d] = o;
}

// ---------------------------------------------------------------------------
extern "C" void kernel_launch(void* const* d_in, const int* in_sizes, int n_in,
                              void* d_out, int out_size)
{
    const float* hidden = (const float*)d_in[0];   // (4, 8192, 4096)
    const float* w_kv   = (const float*)d_in[1];   // (4096, 256)
    const float* w_gate = (const float*)d_in[2];   // (4096, 256)
    const float* pbias  = (const float*)d_in[3];   // (64, 128)
    float* out = (float*)d_out;                    // (4, 256, 128)

    cudaFuncSetAttribute(gemm_kernel,
                         cudaFuncAttributeMaxDynamicSharedMemorySize, SMEM_GEMM);

    convW_kernel<<<dim3(H_DIM / 256, N_TOT), 256>>>(w_kv, w_gate);

    // grid.x fastest: the 4 column-block CTAs sharing one A row-slab are
    // adjacent bids -> concurrent -> A k-stripes served from L2.
    dim3 ggrid(N_TOT / 128, M_TOT / 128);   // (4, 256)
    gemm_kernel<<<ggrid, 256, SMEM_GEMM>>>(hidden);

    pool_kernel<<<B_DIM * (S_DIM / RATIO), 128>>>(pbias, out);
}